// round 4
// baseline (speedup 1.0000x reference)
#include <cuda_runtime.h>
#include <math.h>

#define TT   1024
#define NA   512
#define MB   64
#define NM   32768                       // NA*MB elements per timestep slab
#define HALF ((size_t)NM * TT)           // 33,554,432 elements per output tensor

// ---------------- scratch (device globals; allocation is forbidden) -------------
__device__ float g_X2[(size_t)TT * NM];          // [t][n][m] transposed x; reused for Y
__device__ float g_P [(size_t)TT * NM];          // [t][a][m] = Wax@x + ba
__device__ float g_A [((size_t)TT + 1) * NM];    // slot 0 = a0; slot t+1 = a_{t+1}
__device__ volatile int g_done[TT + 1];          // per-step completion counters

// ---------------- init: zero flags, seed a0 into slot 0 -------------------------
__global__ void k_init(const float* __restrict__ a0) {
    if (blockIdx.x == 0) {
        for (int i = threadIdx.x; i <= TT; i += blockDim.x)
            g_done[i] = (i == 0) ? 128 : 0;
    } else {
        int idx = (blockIdx.x - 1) * 256 + threadIdx.x;
        g_A[idx] = a0[idx];
    }
}

// ---------------- 32x32 tiled transpose -----------------------------------------
__device__ __forceinline__ void trans_body(const float* __restrict__ src,
                                           float* __restrict__ dst, int R, int C) {
    __shared__ float tile[32][33];
    int c0 = blockIdx.x * 32, r0 = blockIdx.y * 32;
    int tx = threadIdx.x, ty = threadIdx.y;
#pragma unroll
    for (int i = 0; i < 32; i += 8)
        tile[ty + i][tx] = src[(size_t)(r0 + ty + i) * C + (c0 + tx)];
    __syncthreads();
#pragma unroll
    for (int i = 0; i < 32; i += 8)
        dst[(size_t)(c0 + ty + i) * R + (r0 + tx)] = tile[tx][ty + i];
}
__global__ __launch_bounds__(256) void k_trans_x(const float* __restrict__ x) {
    trans_body(x, g_X2, NM, TT);          // [32768][1024] -> [1024][32768]
}
__global__ __launch_bounds__(256) void k_trans_a(float* __restrict__ out) {
    trans_body(g_A + NM, out, TT, NM);    // [1024][32768] -> [32768][1024]
}
__global__ __launch_bounds__(256) void k_trans_y(float* __restrict__ out) {
    trans_body(g_X2, out, TT, NM);
}

// ---------------- batched GEMM: C_t[64 rows x 64 m] = W @ X_t (+bias) ------------
// grid = (8 row-blocks, 1024 t), 256 threads. Thread tile: 4 rows x 4 m.
template <bool SOFTMAX>
__device__ __forceinline__ void gemm_body(const float* __restrict__ W,
                                          const float* __restrict__ bias,
                                          const float* __restrict__ Xbase,
                                          float* __restrict__ Ybase) {
    __shared__ float Ws[64][32];   // [row][k]  8KB
    __shared__ float Xs[32][64];   // [k][m]    8KB

    int t   = blockIdx.y;
    int rb  = blockIdx.x;
    const float* X = Xbase + (size_t)t * NM;
    float*       Y = Ybase + (size_t)t * NM;
    int tid = threadIdx.x;
    int mq  = tid & 15;            // m0 = 4*mq
    int rq  = tid >> 4;            // r0 = 4*rq (16 groups)
    int r0  = rb * 64 + rq * 4;

    float acc[4][4];
#pragma unroll
    for (int i = 0; i < 4; i++)
#pragma unroll
        for (int j = 0; j < 4; j++) acc[i][j] = 0.f;

    for (int kt = 0; kt < 16; kt++) {
        __syncthreads();
        // stage W tile: 64x32 floats = 512 float4, 2 per thread
        {
            int f4 = tid;
            int row = f4 >> 3, c4 = f4 & 7;
            *(float4*)&Ws[row][c4 * 4] =
                *(const float4*)&W[(size_t)(rb * 64 + row) * NA + kt * 32 + c4 * 4];
            f4 = tid + 256;
            row = f4 >> 3; c4 = f4 & 7;
            *(float4*)&Ws[row][c4 * 4] =
                *(const float4*)&W[(size_t)(rb * 64 + row) * NA + kt * 32 + c4 * 4];
        }
        // stage X tile: 32x64 floats = 512 float4, 2 per thread (coalesced)
        {
            int f4 = tid;
            int k = f4 >> 4, m4 = f4 & 15;
            *(float4*)&Xs[k][m4 * 4] =
                *(const float4*)&X[(size_t)(kt * 32 + k) * MB + m4 * 4];
            f4 = tid + 256;
            k = f4 >> 4; m4 = f4 & 15;
            *(float4*)&Xs[k][m4 * 4] =
                *(const float4*)&X[(size_t)(kt * 32 + k) * MB + m4 * 4];
        }
        __syncthreads();
#pragma unroll 8
        for (int k = 0; k < 32; k++) {
            float4 xv = *(const float4*)&Xs[k][mq * 4];
#pragma unroll
            for (int i = 0; i < 4; i++) {
                float w = Ws[rq * 4 + i][k];
                acc[i][0] += w * xv.x;
                acc[i][1] += w * xv.y;
                acc[i][2] += w * xv.z;
                acc[i][3] += w * xv.w;
            }
        }
    }

    if (!SOFTMAX) {
#pragma unroll
        for (int i = 0; i < 4; i++) {
            float b = bias[r0 + i];
            float4 v = make_float4(acc[i][0] + b, acc[i][1] + b,
                                   acc[i][2] + b, acc[i][3] + b);
            *(float4*)&Y[(size_t)(r0 + i) * MB + mq * 4] = v;
        }
    } else {
        // softmax over the m axis (64 values per row, spread over 16 lanes x 4)
#pragma unroll
        for (int i = 0; i < 4; i++) {
            float b  = bias[r0 + i];
            float v0 = acc[i][0] + b, v1 = acc[i][1] + b;
            float v2 = acc[i][2] + b, v3 = acc[i][3] + b;
            float mx = fmaxf(fmaxf(v0, v1), fmaxf(v2, v3));
#pragma unroll
            for (int o = 1; o < 16; o <<= 1)
                mx = fmaxf(mx, __shfl_xor_sync(0xffffffffu, mx, o));
            float e0 = __expf(v0 - mx), e1 = __expf(v1 - mx);
            float e2 = __expf(v2 - mx), e3 = __expf(v3 - mx);
            float s = e0 + e1 + e2 + e3;
#pragma unroll
            for (int o = 1; o < 16; o <<= 1)
                s += __shfl_xor_sync(0xffffffffu, s, o);
            float inv = 1.0f / s;
            *(float4*)&Y[(size_t)(r0 + i) * MB + mq * 4] =
                make_float4(e0 * inv, e1 * inv, e2 * inv, e3 * inv);
        }
    }
}

__global__ __launch_bounds__(256) void k_gemmP(const float* __restrict__ Wax,
                                               const float* __restrict__ ba) {
    gemm_body<false>(Wax, ba, g_X2, g_P);
}
__global__ __launch_bounds__(256) void k_gemmY(const float* __restrict__ Wya,
                                               const float* __restrict__ by) {
    gemm_body<true>(Wya, by, g_A + NM, g_X2);
}

// ---------------- persistent recurrence: 128 CTAs, flag-synced steps -------------
// CTA = (8 rows) x (32 m-half). Waa rows resident in SMEM for all 1024 steps.
__global__ __launch_bounds__(128) void k_recur(const float* __restrict__ Waa) {
    __shared__ float Was[8][512];   // 16KB, resident weights
    __shared__ float As[128][32];   // 16KB, a_prev k-tile staging

    int bid  = blockIdx.x;          // 0..127
    int rb   = bid >> 1;            // 64 row blocks of 8
    int mh   = bid & 1;             // m half
    int tid  = threadIdx.x;
    int m    = tid & 31;
    int rloc = (tid >> 5) * 2;      // local rows rloc, rloc+1
    int r0   = rb * 8 + rloc;
    int mg   = mh * 32 + m;

    // load Waa rows once: 4096 floats = 1024 float4, 8 per thread
#pragma unroll
    for (int i = 0; i < 8; i++) {
        int f4  = tid + i * 128;
        int row = f4 >> 7;
        int c4  = f4 & 127;
        *(float4*)&Was[row][c4 * 4] =
            *(const float4*)&Waa[(size_t)(rb * 8 + row) * NA + c4 * 4];
    }
    __syncthreads();

    for (int s = 0; s < TT; s++) {
        if (tid == 0) {
            while (g_done[s] < 128) { }   // volatile spin: wait for slot s complete
        }
        __syncthreads();

        const float* Ap = g_A + (size_t)s * NM;
        float acc0 = 0.f, acc0b = 0.f, acc1 = 0.f, acc1b = 0.f;

        for (int ktile = 0; ktile < 4; ktile++) {
            // stage a_prev[ktile*128 .. +128][mh*32 .. +32]: 1024 float4, 8/thread
#pragma unroll
            for (int i = 0; i < 8; i++) {
                int f4 = tid + i * 128;
                int k  = f4 >> 3;
                int c4 = f4 & 7;
                *(float4*)&As[k][c4 * 4] =
                    *(const float4*)&Ap[(size_t)(ktile * 128 + k) * MB + mh * 32 + c4 * 4];
            }
            __syncthreads();
            int koff = ktile * 128;
#pragma unroll 8
            for (int k4 = 0; k4 < 32; k4++) {
                int kb = k4 * 4;
                float4 w0 = *(const float4*)&Was[rloc][koff + kb];
                float4 w1 = *(const float4*)&Was[rloc + 1][koff + kb];
                float a0v = As[kb + 0][m];
                float a1v = As[kb + 1][m];
                float a2v = As[kb + 2][m];
                float a3v = As[kb + 3][m];
                acc0  += w0.x * a0v;  acc0b += w0.y * a1v;
                acc0  += w0.z * a2v;  acc0b += w0.w * a3v;
                acc1  += w1.x * a0v;  acc1b += w1.y * a1v;
                acc1  += w1.z * a2v;  acc1b += w1.w * a3v;
            }
            __syncthreads();
        }

        size_t o0 = (size_t)r0 * MB + mg;
        size_t o1 = o0 + MB;
        const float* P  = g_P + (size_t)s * NM;
        float*       An = g_A + (size_t)(s + 1) * NM;
        An[o0] = tanhf(acc0 + acc0b + P[o0]);
        An[o1] = tanhf(acc1 + acc1b + P[o1]);

        __threadfence();
        __syncthreads();
        if (tid == 0) atomicAdd((int*)&g_done[s + 1], 1);
    }
}

// ---------------- launch ----------------------------------------------------------
extern "C" void kernel_launch(void* const* d_in, const int* in_sizes, int n_in,
                              void* d_out, int out_size) {
    (void)in_sizes; (void)n_in; (void)out_size;
    const float* x   = (const float*)d_in[0];
    const float* a0  = (const float*)d_in[1];
    const float* Waa = (const float*)d_in[2];
    const float* Wax = (const float*)d_in[3];
    const float* Wya = (const float*)d_in[4];
    const float* ba  = (const float*)d_in[5];
    const float* by  = (const float*)d_in[6];
    float* out = (float*)d_out;

    k_init<<<129, 256>>>(a0);
    k_trans_x<<<dim3(TT / 32, NM / 32), dim3(32, 8)>>>(x);     // x -> [t][n][m]
    k_gemmP<<<dim3(8, TT), 256>>>(Wax, ba);                    // P = Wax@X + ba
    k_recur<<<128, 128>>>(Waa);                                // a_t chain
    k_gemmY<<<dim3(8, TT), 256>>>(Wya, by);                    // Y = softmax(Wya@A + by)
    k_trans_a<<<dim3(NM / 32, TT / 32), dim3(32, 8)>>>(out);           // -> [n][m][t]
    k_trans_y<<<dim3(NM / 32, TT / 32), dim3(32, 8)>>>(out + HALF);
}